// round 1
// baseline (speedup 1.0000x reference)
#include <cuda_runtime.h>

#define NBATCH 4
#define ACH    16
#define HH     384
#define WWID   384
#define HW     (HH*WWID)
#define NB     95
#define NBB    (NB*NB)
#define WPC    4
#define NS_ITERS 10
#define MST    20   // shared row stride in floats (16B-aligned, conflict-friendly)

// One warp handles one (image n, block b) task:
//   gather 64x16 tile M, G = M^T M, scale by inf-norm,
//   coupled Newton-Schulz -> Z ~ A^{-1/2}, W = I - 2*rsqrt(bound)*Z,
//   scatter-add M*W into out.
__global__ __launch_bounds__(128) void llr_main(const float* __restrict__ x,
                                                float* __restrict__ out)
{
    __shared__ float sh[WPC][64*MST + 3*16*MST];
    const int w = threadIdx.x >> 5;
    const int l = threadIdx.x & 31;
    const int task = blockIdx.x * WPC + w;

    float* Ms = sh[w];
    float* Y  = Ms + 64*MST;
    float* Zm = Y  + 16*MST;
    float* Tm = Zm + 16*MST;

    const int n  = task / NBB;
    const int b  = task - n*NBB;
    const int by = b / NB;
    const int bx = b - by*NB;
    const int base = (by*4)*WWID + bx*4;
    const float* xn = x + (size_t)n * ACH * HW;

    // ---- gather 64x16 block into shared ----
    #pragma unroll
    for (int h = 0; h < 2; h++) {
        const int p = l + 32*h;
        const int pix = base + (p >> 3)*WWID + (p & 7);
        #pragma unroll
        for (int a = 0; a < ACH; a++) {
            Ms[p*MST + a] = xn[a*HW + pix];
        }
    }
    __syncwarp();

    // ---- G = M^T M : lane covers row i, cols jb..jb+7 ----
    const int i  = l >> 1;
    const int jb = (l & 1) * 8;
    float g[8];
    #pragma unroll
    for (int k = 0; k < 8; k++) g[k] = 0.f;
    #pragma unroll 4
    for (int p = 0; p < 64; p++) {
        const float  mi = Ms[p*MST + i];
        const float4 b0 = *(const float4*)&Ms[p*MST + jb];
        const float4 b1 = *(const float4*)&Ms[p*MST + jb + 4];
        g[0] += mi*b0.x; g[1] += mi*b0.y; g[2] += mi*b0.z; g[3] += mi*b0.w;
        g[4] += mi*b1.x; g[5] += mi*b1.y; g[6] += mi*b1.z; g[7] += mi*b1.w;
    }

    // inf-norm bound (>= lambda_max), warp-uniform
    float rsum = 0.f;
    #pragma unroll
    for (int k = 0; k < 8; k++) rsum += fabsf(g[k]);
    rsum += __shfl_xor_sync(0xffffffffu, rsum, 1);   // full row sum
    float bound = rsum;
    #pragma unroll
    for (int off = 2; off <= 16; off <<= 1)
        bound = fmaxf(bound, __shfl_xor_sync(0xffffffffu, bound, off));
    bound = fmaxf(bound, 1e-20f);
    const float sc = 1.0f / bound;
    const float rs = rsqrtf(bound);

    // Y = G*sc (spectrum in (0,1]) ; Z = I
    #pragma unroll
    for (int k = 0; k < 8; k++) {
        Y[i*MST + jb + k]  = g[k]*sc;
        Zm[i*MST + jb + k] = (i == jb + k) ? 1.f : 0.f;
    }
    __syncwarp();

    // ---- coupled Newton-Schulz: T=(3I - Z*Y)/2; Y=Y*T; Z=T*Z ----
    for (int it = 0; it < NS_ITERS; it++) {
        float t[8];
        #pragma unroll
        for (int k = 0; k < 8; k++) t[k] = 0.f;
        #pragma unroll
        for (int k = 0; k < 16; k++) {
            const float  zv = Zm[i*MST + k];
            const float4 ya = *(const float4*)&Y[k*MST + jb];
            const float4 yb = *(const float4*)&Y[k*MST + jb + 4];
            t[0] += zv*ya.x; t[1] += zv*ya.y; t[2] += zv*ya.z; t[3] += zv*ya.w;
            t[4] += zv*yb.x; t[5] += zv*yb.y; t[6] += zv*yb.z; t[7] += zv*yb.w;
        }
        #pragma unroll
        for (int k = 0; k < 8; k++) {
            float v = -0.5f * t[k];
            if (i == jb + k) v += 1.5f;
            Tm[i*MST + jb + k] = v;
        }
        __syncwarp();

        float yn[8], zn[8];
        #pragma unroll
        for (int k = 0; k < 8; k++) { yn[k] = 0.f; zn[k] = 0.f; }
        #pragma unroll
        for (int k = 0; k < 16; k++) {
            const float  yv = Y[i*MST + k];
            const float  tv = Tm[i*MST + k];
            const float4 ta = *(const float4*)&Tm[k*MST + jb];
            const float4 tb = *(const float4*)&Tm[k*MST + jb + 4];
            const float4 za = *(const float4*)&Zm[k*MST + jb];
            const float4 zb = *(const float4*)&Zm[k*MST + jb + 4];
            yn[0] += yv*ta.x; yn[1] += yv*ta.y; yn[2] += yv*ta.z; yn[3] += yv*ta.w;
            yn[4] += yv*tb.x; yn[5] += yv*tb.y; yn[6] += yv*tb.z; yn[7] += yv*tb.w;
            zn[0] += tv*za.x; zn[1] += tv*za.y; zn[2] += tv*za.z; zn[3] += tv*za.w;
            zn[4] += tv*zb.x; zn[5] += tv*zb.y; zn[6] += tv*zb.z; zn[7] += tv*zb.w;
        }
        __syncwarp();   // all reads of Y/Z done before overwrite
        #pragma unroll
        for (int k = 0; k < 8; k++) {
            Y[i*MST + jb + k]  = yn[k];
            Zm[i*MST + jb + k] = zn[k];
        }
        __syncwarp();
    }

    // ---- out_block = M * (I - 2*rs*Z), atomic scatter ----
    const int j  = l & 15;
    const int ph = l >> 4;
    float wc[16];
    #pragma unroll
    for (int c = 0; c < 16; c++) {
        wc[c] = ((c == j) ? 1.f : 0.f) - 2.f*rs*Zm[c*MST + j];
    }
    float* outj = out + ((size_t)n*ACH + j)*HW + base;
    #pragma unroll 4
    for (int t2 = 0; t2 < 32; t2++) {
        const int p = ph*32 + t2;
        const float4 m0 = *(const float4*)&Ms[p*MST + 0];
        const float4 m1 = *(const float4*)&Ms[p*MST + 4];
        const float4 m2 = *(const float4*)&Ms[p*MST + 8];
        const float4 m3 = *(const float4*)&Ms[p*MST + 12];
        const float acc =
              m0.x*wc[0]  + m0.y*wc[1]  + m0.z*wc[2]  + m0.w*wc[3]
            + m1.x*wc[4]  + m1.y*wc[5]  + m1.z*wc[6]  + m1.w*wc[7]
            + m2.x*wc[8]  + m2.y*wc[9]  + m2.z*wc[10] + m2.w*wc[11]
            + m3.x*wc[12] + m3.y*wc[13] + m3.z*wc[14] + m3.w*wc[15];
        atomicAdd(&outj[(p >> 3)*WWID + (p & 7)], acc);
    }
}

__global__ void llr_div(float4* __restrict__ out, const float4* __restrict__ bw4)
{
    const int idx = blockIdx.x * blockDim.x + threadIdx.x;
    const int total = NBATCH*ACH*HW/4;
    if (idx < total) {
        float4 o   = out[idx];
        const float4 bw = bw4[idx % (HW/4)];
        o.x /= bw.x; o.y /= bw.y; o.z /= bw.z; o.w /= bw.w;
        out[idx] = o;
    }
}

extern "C" void kernel_launch(void* const* d_in, const int* in_sizes, int n_in,
                              void* d_out, int out_size)
{
    const float* x  = (const float*)d_in[0];
    const float* bw = (const float*)d_in[1];
    float* out = (float*)d_out;

    cudaMemsetAsync(out, 0, (size_t)out_size * sizeof(float));
    llr_main<<<NBB, WPC*32>>>(x, out);
    const int total4 = NBATCH*ACH*HW/4;
    llr_div<<<(total4 + 255)/256, 256>>>((float4*)out, (const float4*)bw);
}

// round 2
// speedup vs baseline: 2.0293x; 2.0293x over previous
#include <cuda_runtime.h>

#define ACH    16
#define WWID   384
#define HW     (384*384)
#define NB     95
#define NBB    (NB*NB)
#define NTASK  (4*NBB)
#define MST    20

// 16x16 W matrices, one per (n, by, bx) task.  4*9025*256 floats = 36.97 MB.
__device__ float4 g_Wv[(size_t)NTASK*64];
#define g_W ((float*)g_Wv)

// ---------------------------------------------------------------------------
// Kernel 1: per (n, block): G = M^T M, A = G * 2/||G||_inf,
// coupled Newton-Schulz (1 simplified + 8 full iters) -> Z ~ A^{-1/2},
// W = I - 2*sqrt(sc)*Z  written to g_W.
// One warp per task. A/Z/Y rows live in registers (pair-shuffle for the
// other half); only Y and T sit in shared as broadcast B-operands.
// ---------------------------------------------------------------------------
__global__ __launch_bounds__(128) void llr_factor(const float* __restrict__ x)
{
    __shared__ __align__(16) float sh[4][64*MST];
    const int w = threadIdx.x >> 5;
    const int l = threadIdx.x & 31;
    const int task = blockIdx.x*4 + w;

    float* Ms = sh[w];
    float* Ym = Ms;             // overlaps M tile (dead after G phase)
    float* Tm = Ms + 16*MST;

    const int n  = task / NBB;
    const int b  = task - n*NBB;
    const int by = b / NB;
    const int bx = b - by*NB;
    const int base = (by*4)*WWID + bx*4;
    const float* xn = x + (size_t)n*ACH*HW;

    // gather 64x16 tile
    #pragma unroll
    for (int h = 0; h < 2; h++) {
        const int p = l + 32*h;
        const int pix = base + (p>>3)*WWID + (p&7);
        #pragma unroll
        for (int a = 0; a < ACH; a++)
            Ms[p*MST + a] = xn[(size_t)a*HW + pix];
    }
    __syncwarp();

    const int i  = l >> 1;
    const int jb = (l & 1) * 8;

    // G row i, cols jb..jb+7
    float g[8];
    #pragma unroll
    for (int k = 0; k < 8; k++) g[k] = 0.f;
    #pragma unroll 4
    for (int p = 0; p < 64; p++) {
        const float  mi = Ms[p*MST + i];
        const float4 b0 = *(const float4*)&Ms[p*MST + jb];
        const float4 b1 = *(const float4*)&Ms[p*MST + jb + 4];
        g[0] = fmaf(mi, b0.x, g[0]); g[1] = fmaf(mi, b0.y, g[1]);
        g[2] = fmaf(mi, b0.z, g[2]); g[3] = fmaf(mi, b0.w, g[3]);
        g[4] = fmaf(mi, b1.x, g[4]); g[5] = fmaf(mi, b1.y, g[5]);
        g[6] = fmaf(mi, b1.z, g[6]); g[7] = fmaf(mi, b1.w, g[7]);
    }

    // inf-norm bound (>= lambda_max), warp-uniform
    float rsum = 0.f;
    #pragma unroll
    for (int k = 0; k < 8; k++) rsum += fabsf(g[k]);
    rsum += __shfl_xor_sync(0xffffffffu, rsum, 1);
    float bound = rsum;
    #pragma unroll
    for (int off = 2; off <= 16; off <<= 1)
        bound = fmaxf(bound, __shfl_xor_sync(0xffffffffu, bound, off));
    bound = fmaxf(bound, 1e-20f);
    const float sc = 2.0f / bound;        // spectrum of A in (0, 2]
    const float w2 = 2.0f * sqrtf(sc);    // W = I - w2 * Z_final

    float a[8];
    #pragma unroll
    for (int k = 0; k < 8; k++) a[k] = g[k]*sc;

    __syncwarp();   // all Ms reads done; Ym/Tm regions may be reused

    // --- iter 1 (simplified): T0 = 1.5I - 0.5A ; Z = T0 ; Y = A*T0 ---
    float z[8];
    #pragma unroll
    for (int m = 0; m < 8; m++)
        z[m] = ((i == jb+m) ? 1.5f : 0.f) - 0.5f*a[m];
    {
        float4 s0 = make_float4(z[0],z[1],z[2],z[3]);
        float4 s1 = make_float4(z[4],z[5],z[6],z[7]);
        *(float4*)&Tm[i*MST+jb]   = s0;
        *(float4*)&Tm[i*MST+jb+4] = s1;
    }
    __syncwarp();

    float ar[16];
    #pragma unroll
    for (int m = 0; m < 8; m++) {
        const float o = __shfl_xor_sync(0xffffffffu, a[m], 1);
        ar[m]   = (l&1) ? o    : a[m];
        ar[m+8] = (l&1) ? a[m] : o;
    }
    float y[8];
    #pragma unroll
    for (int m = 0; m < 8; m++) y[m] = 0.f;
    #pragma unroll
    for (int k = 0; k < 16; k++) {
        const float4 b0 = *(const float4*)&Tm[k*MST+jb];
        const float4 b1 = *(const float4*)&Tm[k*MST+jb+4];
        y[0] = fmaf(ar[k], b0.x, y[0]); y[1] = fmaf(ar[k], b0.y, y[1]);
        y[2] = fmaf(ar[k], b0.z, y[2]); y[3] = fmaf(ar[k], b0.w, y[3]);
        y[4] = fmaf(ar[k], b1.x, y[4]); y[5] = fmaf(ar[k], b1.y, y[5]);
        y[6] = fmaf(ar[k], b1.z, y[6]); y[7] = fmaf(ar[k], b1.w, y[7]);
    }
    {
        float4 s0 = make_float4(y[0],y[1],y[2],y[3]);
        float4 s1 = make_float4(y[4],y[5],y[6],y[7]);
        *(float4*)&Ym[i*MST+jb]   = s0;
        *(float4*)&Ym[i*MST+jb+4] = s1;
    }
    __syncwarp();

    // --- 8 full iterations: T = 1.5I - 0.5*Z*Y ; Y = Y*T ; Z = Z*T ---
    #pragma unroll 1
    for (int it = 0; it < 8; it++) {
        float zr[16];
        #pragma unroll
        for (int m = 0; m < 8; m++) {
            const float o = __shfl_xor_sync(0xffffffffu, z[m], 1);
            zr[m]   = (l&1) ? o    : z[m];
            zr[m+8] = (l&1) ? z[m] : o;
        }
        float t[8];
        #pragma unroll
        for (int m = 0; m < 8; m++) t[m] = 0.f;
        #pragma unroll
        for (int k = 0; k < 16; k++) {
            const float4 b0 = *(const float4*)&Ym[k*MST+jb];
            const float4 b1 = *(const float4*)&Ym[k*MST+jb+4];
            t[0] = fmaf(zr[k], b0.x, t[0]); t[1] = fmaf(zr[k], b0.y, t[1]);
            t[2] = fmaf(zr[k], b0.z, t[2]); t[3] = fmaf(zr[k], b0.w, t[3]);
            t[4] = fmaf(zr[k], b1.x, t[4]); t[5] = fmaf(zr[k], b1.y, t[5]);
            t[6] = fmaf(zr[k], b1.z, t[6]); t[7] = fmaf(zr[k], b1.w, t[7]);
        }
        #pragma unroll
        for (int m = 0; m < 8; m++)
            t[m] = fmaf(t[m], -0.5f, (i == jb+m) ? 1.5f : 0.f);
        {
            float4 s0 = make_float4(t[0],t[1],t[2],t[3]);
            float4 s1 = make_float4(t[4],t[5],t[6],t[7]);
            *(float4*)&Tm[i*MST+jb]   = s0;
            *(float4*)&Tm[i*MST+jb+4] = s1;
        }
        __syncwarp();

        float yr[16];
        #pragma unroll
        for (int m = 0; m < 8; m++) {
            const float o = __shfl_xor_sync(0xffffffffu, y[m], 1);
            yr[m]   = (l&1) ? o    : y[m];
            yr[m+8] = (l&1) ? y[m] : o;
        }
        float yn[8], zn[8];
        #pragma unroll
        for (int m = 0; m < 8; m++) { yn[m] = 0.f; zn[m] = 0.f; }
        #pragma unroll
        for (int k = 0; k < 16; k++) {
            const float4 b0 = *(const float4*)&Tm[k*MST+jb];
            const float4 b1 = *(const float4*)&Tm[k*MST+jb+4];
            yn[0] = fmaf(yr[k], b0.x, yn[0]); yn[1] = fmaf(yr[k], b0.y, yn[1]);
            yn[2] = fmaf(yr[k], b0.z, yn[2]); yn[3] = fmaf(yr[k], b0.w, yn[3]);
            yn[4] = fmaf(yr[k], b1.x, yn[4]); yn[5] = fmaf(yr[k], b1.y, yn[5]);
            yn[6] = fmaf(yr[k], b1.z, yn[6]); yn[7] = fmaf(yr[k], b1.w, yn[7]);
            zn[0] = fmaf(zr[k], b0.x, zn[0]); zn[1] = fmaf(zr[k], b0.y, zn[1]);
            zn[2] = fmaf(zr[k], b0.z, zn[2]); zn[3] = fmaf(zr[k], b0.w, zn[3]);
            zn[4] = fmaf(zr[k], b1.x, zn[4]); zn[5] = fmaf(zr[k], b1.y, zn[5]);
            zn[6] = fmaf(zr[k], b1.z, zn[6]); zn[7] = fmaf(zr[k], b1.w, zn[7]);
        }
        #pragma unroll
        for (int m = 0; m < 8; m++) { y[m] = yn[m]; z[m] = zn[m]; }
        {
            float4 s0 = make_float4(y[0],y[1],y[2],y[3]);
            float4 s1 = make_float4(y[4],y[5],y[6],y[7]);
            *(float4*)&Ym[i*MST+jb]   = s0;
            *(float4*)&Ym[i*MST+jb+4] = s1;
        }
        __syncwarp();
    }

    // --- W = I - w2*Z, coalesced store (1 KB per warp) ---
    float* wp = g_W + (size_t)task*256 + i*16 + jb;
    float4 o0, o1;
    o0.x = ((i == jb+0) ? 1.f : 0.f) - w2*z[0];
    o0.y = ((i == jb+1) ? 1.f : 0.f) - w2*z[1];
    o0.z = ((i == jb+2) ? 1.f : 0.f) - w2*z[2];
    o0.w = ((i == jb+3) ? 1.f : 0.f) - w2*z[3];
    o1.x = ((i == jb+4) ? 1.f : 0.f) - w2*z[4];
    o1.y = ((i == jb+5) ? 1.f : 0.f) - w2*z[5];
    o1.z = ((i == jb+6) ? 1.f : 0.f) - w2*z[6];
    o1.w = ((i == jb+7) ? 1.f : 0.f) - w2*z[7];
    *(float4*)wp     = o0;
    *(float4*)(wp+4) = o1;
}

// ---------------------------------------------------------------------------
// Kernel 2: per (4x4 cell, n): Wsum = sum of <=4 covering W matrices,
// out[n, :, p] = Wsum^T x[n, :, p] / bw[p] for the 16 pixels of the cell.
// One warp per (cell, n); 4 warps of a CTA share one cell.
// ---------------------------------------------------------------------------
__global__ __launch_bounds__(128) void llr_apply(const float* __restrict__ x,
                                                 const float* __restrict__ bw,
                                                 float* __restrict__ out)
{
    __shared__ __align__(16) float ws_s[4][256];
    __shared__ __align__(16) float xs_s[4][16*17];
    const int w  = threadIdx.x >> 5;
    const int l  = threadIdx.x & 31;
    const int gy = blockIdx.x / 96;
    const int gx = blockIdx.x - gy*96;
    const int n  = w;
    float* ws = ws_s[w];
    float* xs = xs_s[w];

    // Wsum over covering blocks (by in {gy-1,gy}, bx in {gx-1,gx}, clamped)
    float4 A0 = make_float4(0,0,0,0), A1 = make_float4(0,0,0,0);
    #pragma unroll
    for (int dy = 0; dy < 2; dy++) {
        const int by = gy - 1 + dy;
        if (by < 0 || by >= NB) continue;
        #pragma unroll
        for (int dx = 0; dx < 2; dx++) {
            const int bx = gx - 1 + dx;
            if (bx < 0 || bx >= NB) continue;
            const float* wp = g_W + ((size_t)n*NBB + by*NB + bx)*256 + l*8;
            const float4 u0 = *(const float4*)wp;
            const float4 u1 = *(const float4*)(wp + 4);
            A0.x += u0.x; A0.y += u0.y; A0.z += u0.z; A0.w += u0.w;
            A1.x += u1.x; A1.y += u1.y; A1.z += u1.z; A1.w += u1.w;
        }
    }
    *(float4*)&ws[l*8]     = A0;
    *(float4*)&ws[l*8 + 4] = A1;

    // x patch: 16 channels x 4x4 pixels -> xs[p*17 + i]
    const int ich = l >> 1;
    const int r0  = (l & 1) * 2;
    const int hb  = gy*4, wb = gx*4;
    const float* xp = x + ((size_t)n*ACH + ich)*HW;
    #pragma unroll
    for (int dr = 0; dr < 2; dr++) {
        const int r = r0 + dr;
        const float4 v = *(const float4*)&xp[(hb + r)*WWID + wb];
        xs[(r*4+0)*17 + ich] = v.x;
        xs[(r*4+1)*17 + ich] = v.y;
        xs[(r*4+2)*17 + ich] = v.z;
        xs[(r*4+3)*17 + ich] = v.w;
    }
    __syncwarp();

    // out[n, jb..jb+7, pixel p] ; lane: p = l>>1, jb = (l&1)*8
    const int p  = l >> 1;
    const int jb = (l & 1) * 8;
    float acc[8];
    #pragma unroll
    for (int m = 0; m < 8; m++) acc[m] = 0.f;
    #pragma unroll
    for (int k = 0; k < 16; k++) {
        const float  xv = xs[p*17 + k];
        const float4 b0 = *(const float4*)&ws[k*16 + jb];
        const float4 b1 = *(const float4*)&ws[k*16 + jb + 4];
        acc[0] = fmaf(xv, b0.x, acc[0]); acc[1] = fmaf(xv, b0.y, acc[1]);
        acc[2] = fmaf(xv, b0.z, acc[2]); acc[3] = fmaf(xv, b0.w, acc[3]);
        acc[4] = fmaf(xv, b1.x, acc[4]); acc[5] = fmaf(xv, b1.y, acc[5]);
        acc[6] = fmaf(xv, b1.z, acc[6]); acc[7] = fmaf(xv, b1.w, acc[7]);
    }
    const int h  = hb + (p >> 2);
    const int wc = wb + (p & 3);
    const float inv = 1.0f / bw[h*WWID + wc];   // weights are powers of 2: exact
    float* op = out + ((size_t)n*ACH + jb)*HW + h*WWID + wc;
    #pragma unroll
    for (int m = 0; m < 8; m++)
        op[(size_t)m*HW] = acc[m]*inv;
}

extern "C" void kernel_launch(void* const* d_in, const int* in_sizes, int n_in,
                              void* d_out, int out_size)
{
    const float* x  = (const float*)d_in[0];
    const float* bw = (const float*)d_in[1];
    float* out = (float*)d_out;

    llr_factor<<<NBB, 128>>>(x);        // 9025 CTAs x 4 warps = 36100 tasks
    llr_apply<<<96*96, 128>>>(x, bw, out);
}